// round 5
// baseline (speedup 1.0000x reference)
#include <cuda_runtime.h>

// ---------------------------------------------------------------------------
// Problem constants
// ---------------------------------------------------------------------------
#define D_IN   120000
#define BATCH  512
#define H1     600
#define H2     300
#define H3     200

// Layer-1 nnz are counting-sorted by key = row * NB1 + (col >> CB_SHIFT)
// (row-major, 512-column blocks) so all 600 row-CTAs sweep xT in lockstep
// and the L2 working set is a narrow band.
#define CB_SHIFT 9
#define NB1      235           // ceil(120000 / 512)

// Bin layout (concatenated across layers so one global exclusive scan gives
// final positions into the shared pairs buffer directly):
#define BASE1 0
#define BINS1 (H1 * NB1)       // 141000
#define BASE2 (BASE1 + BINS1)  // 141000
#define BASE3 (BASE2 + H1)     // 141600
#define BASE4 (BASE3 + H2)     // 141900
#define BASE5 (BASE4 + H3)     // 142100
#define BINS_TOTAL (BASE5 + H3) // 142300

#define MAX_PAIRS 7300000      // total nnz = 7,264,000

// ---------------------------------------------------------------------------
// Static device scratch (allocation-free rule: __device__ globals)
// ---------------------------------------------------------------------------
__device__ float  g_xT[(size_t)D_IN * BATCH];   // 245.76 MB, x transposed [D][B]
__device__ float2 g_pairs[MAX_PAIRS];           // (col bits, val) sorted by bin
__device__ int    g_binCnt[BINS_TOTAL + 1];
__device__ int    g_binPtr[BINS_TOTAL + 1];
__device__ int    g_binFill[BINS_TOTAL + 1];
__device__ float  g_h1[H1 * BATCH];
__device__ float  g_h2[H1 * BATCH];
__device__ float  g_h3[H2 * BATCH];
__device__ float  g_h4[H3 * BATCH];

// ---------------------------------------------------------------------------
// 0) zero bin counters
// ---------------------------------------------------------------------------
__global__ void zero_bins_kernel() {
    int i = blockIdx.x * blockDim.x + threadIdx.x;
    if (i <= BINS_TOTAL) { g_binCnt[i] = 0; g_binFill[i] = 0; }
}

// ---------------------------------------------------------------------------
// 1) transpose x [B][D] -> g_xT [D][B]   (32x32 shared tile, coalesced both sides)
// ---------------------------------------------------------------------------
__global__ void transpose_x_kernel(const float* __restrict__ x) {
    __shared__ float tile[32][33];
    int c0 = blockIdx.x * 32;
    int b0 = blockIdx.y * 32;
    int tx = threadIdx.x, ty = threadIdx.y;
#pragma unroll
    for (int i = 0; i < 32; i += 8)
        tile[ty + i][tx] = x[(size_t)(b0 + ty + i) * D_IN + (c0 + tx)];
    __syncthreads();
#pragma unroll
    for (int i = 0; i < 32; i += 8)
        g_xT[(size_t)(c0 + ty + i) * BATCH + (b0 + tx)] = tile[tx][ty + i];
}

// ---------------------------------------------------------------------------
// 2) histogram nnz into bins.  key = row*nb + (col>>shift); shift=31 -> key=row
// ---------------------------------------------------------------------------
__global__ void hist_kernel(const int* __restrict__ idx, int nnz,
                            int base, int nb, int shift) {
    int j = blockIdx.x * blockDim.x + threadIdx.x;
    if (j >= nnz) return;
    int r = idx[j];
    int c = idx[nnz + j];
    int key = r * nb + (c >> shift);
    atomicAdd(&g_binCnt[base + key], 1);
}

// ---------------------------------------------------------------------------
// 3) exclusive scan over all BINS_TOTAL counters (single CTA, 1024 threads)
// ---------------------------------------------------------------------------
__global__ void scan_kernel() {
    __shared__ int wsum[32];
    __shared__ int s_carry;
    int tid = threadIdx.x, lane = tid & 31, wid = tid >> 5;
    if (tid == 0) s_carry = 0;
    __syncthreads();
    const int N = BINS_TOTAL;
    for (int base = 0; base < N; base += 1024) {
        int i = base + tid;
        int v0 = (i < N) ? g_binCnt[i] : 0;
        int v = v0;
#pragma unroll
        for (int d = 1; d < 32; d <<= 1) {
            int t = __shfl_up_sync(0xFFFFFFFFu, v, d);
            if (lane >= d) v += t;
        }
        if (lane == 31) wsum[wid] = v;
        __syncthreads();
        if (wid == 0) {
            int w = wsum[lane];
#pragma unroll
            for (int d = 1; d < 32; d <<= 1) {
                int t = __shfl_up_sync(0xFFFFFFFFu, w, d);
                if (lane >= d) w += t;
            }
            wsum[lane] = w;
        }
        __syncthreads();
        int carry = s_carry;
        int pre = (wid > 0) ? wsum[wid - 1] : 0;
        if (i < N) g_binPtr[i] = carry + pre + (v - v0);
        int chunk_total = wsum[31];
        __syncthreads();
        if (tid == 0) s_carry = carry + chunk_total;
        __syncthreads();
    }
    if (tid == 0) g_binPtr[N] = s_carry;
}

// ---------------------------------------------------------------------------
// 4) scatter (col, val) pairs to their sorted positions
// ---------------------------------------------------------------------------
__global__ void scatter_kernel(const int* __restrict__ idx,
                               const float* __restrict__ val, int nnz,
                               int base, int nb, int shift) {
    int j = blockIdx.x * blockDim.x + threadIdx.x;
    if (j >= nnz) return;
    int r = idx[j];
    int c = idx[nnz + j];
    int key = base + r * nb + (c >> shift);
    int pos = g_binPtr[key] + atomicAdd(&g_binFill[key], 1);
    g_pairs[pos] = make_float2(__int_as_float(c), val[j]);
}

// ---------------------------------------------------------------------------
// 5) SpMM: one CTA per output row, 512 threads = batch lanes.
//    Fused bias (+BN over batch via block reduce) (+SiLU).
//    mode: 0 = raw, 1 = silu, 2 = bn + silu
// ---------------------------------------------------------------------------
__global__ void __launch_bounds__(512) spmm_kernel(
    const float* __restrict__ inT,      // [in_d][512]
    const float* __restrict__ bias,
    const float* __restrict__ gamma,
    const float* __restrict__ beta,
    float* __restrict__ out,
    int base, int nb, int mode, int outDim, int outTransposed)
{
    __shared__ float2 sh[1024];
    int r = blockIdx.x;
    int tid = threadIdx.x;
    int start = g_binPtr[base + r * nb];
    int end   = g_binPtr[base + (r + 1) * nb];

    float acc = 0.0f;
    for (int b0 = start; b0 < end; b0 += 1024) {
        int n = min(1024, end - b0);
        __syncthreads();
        if (tid < n)       sh[tid]       = g_pairs[b0 + tid];
        if (tid + 512 < n) sh[tid + 512] = g_pairs[b0 + tid + 512];
        __syncthreads();
        int k = 0;
        for (; k + 4 <= n; k += 4) {
            float2 p0 = sh[k], p1 = sh[k + 1], p2 = sh[k + 2], p3 = sh[k + 3];
            float x0 = inT[__float_as_int(p0.x) * BATCH + tid];
            float x1 = inT[__float_as_int(p1.x) * BATCH + tid];
            float x2 = inT[__float_as_int(p2.x) * BATCH + tid];
            float x3 = inT[__float_as_int(p3.x) * BATCH + tid];
            acc += p0.y * x0;
            acc += p1.y * x1;
            acc += p2.y * x2;
            acc += p3.y * x3;
        }
        for (; k < n; k++) {
            float2 p = sh[k];
            acc += p.y * inT[__float_as_int(p.x) * BATCH + tid];
        }
    }
    acc += bias[r];

    float z = acc;
    if (mode >= 2) {
        // BatchNorm over the batch dimension (= this CTA's 512 threads)
        __shared__ float rsum[16], rsum2[16], bcast[2];
        float s = acc, s2 = acc * acc;
#pragma unroll
        for (int d = 16; d; d >>= 1) {
            s  += __shfl_xor_sync(0xFFFFFFFFu, s, d);
            s2 += __shfl_xor_sync(0xFFFFFFFFu, s2, d);
        }
        int lane = tid & 31, wid = tid >> 5;
        if (lane == 0) { rsum[wid] = s; rsum2[wid] = s2; }
        __syncthreads();
        if (wid == 0) {
            float a  = (lane < 16) ? rsum[lane]  : 0.0f;
            float a2 = (lane < 16) ? rsum2[lane] : 0.0f;
#pragma unroll
            for (int d = 8; d; d >>= 1) {
                a  += __shfl_xor_sync(0xFFFFFFFFu, a, d);
                a2 += __shfl_xor_sync(0xFFFFFFFFu, a2, d);
            }
            if (lane == 0) { bcast[0] = a; bcast[1] = a2; }
        }
        __syncthreads();
        float m   = bcast[0] * (1.0f / 512.0f);
        float var = bcast[1] * (1.0f / 512.0f) - m * m;
        z = (acc - m) * rsqrtf(var + 1e-5f) * gamma[r] + beta[r];
    }
    if (mode >= 1) {
        z = z * (1.0f / (1.0f + __expf(-z)));   // silu
    }
    if (outTransposed) out[r * BATCH + tid] = z;
    else               out[(size_t)tid * outDim + r] = z;
}

// ---------------------------------------------------------------------------
// kernel_launch: full pipeline, graph-capturable (kernel launches only)
// ---------------------------------------------------------------------------
extern "C" void kernel_launch(void* const* d_in, const int* in_sizes, int n_in,
                              void* d_out, int out_size) {
    const float* x    = (const float*)d_in[0];
    const int*   idx1 = (const int*)  d_in[1];
    const float* val1 = (const float*)d_in[2];
    const float* b1   = (const float*)d_in[3];
    const int*   idx2 = (const int*)  d_in[4];
    const float* val2 = (const float*)d_in[5];
    const float* b2   = (const float*)d_in[6];
    const int*   idx3 = (const int*)  d_in[7];
    const float* val3 = (const float*)d_in[8];
    const float* b3   = (const float*)d_in[9];
    const int*   idx4 = (const int*)  d_in[10];
    const float* val4 = (const float*)d_in[11];
    const float* b4   = (const float*)d_in[12];
    const int*   idx5 = (const int*)  d_in[13];
    const float* val5 = (const float*)d_in[14];
    const float* b5   = (const float*)d_in[15];
    const float* g1   = (const float*)d_in[16];
    const float* be1  = (const float*)d_in[17];
    const float* g2   = (const float*)d_in[18];
    const float* be2  = (const float*)d_in[19];
    const float* g3   = (const float*)d_in[20];
    const float* be3  = (const float*)d_in[21];

    int nnz1 = in_sizes[1]  / 2;
    int nnz2 = in_sizes[4]  / 2;
    int nnz3 = in_sizes[7]  / 2;
    int nnz4 = in_sizes[10] / 2;
    int nnz5 = in_sizes[13] / 2;

    float *xT, *h1, *h2, *h3, *h4;
    cudaGetSymbolAddress((void**)&xT, g_xT);
    cudaGetSymbolAddress((void**)&h1, g_h1);
    cudaGetSymbolAddress((void**)&h2, g_h2);
    cudaGetSymbolAddress((void**)&h3, g_h3);
    cudaGetSymbolAddress((void**)&h4, g_h4);

    // 0) zero counters
    zero_bins_kernel<<<(BINS_TOTAL + 256) / 256, 256>>>();

    // 1) transpose x -> xT
    transpose_x_kernel<<<dim3(D_IN / 32, BATCH / 32), dim3(32, 8)>>>(x);

    // 2) histograms (layer 1 keyed by (row, col-block); others by row only)
    hist_kernel<<<(nnz1 + 255) / 256, 256>>>(idx1, nnz1, BASE1, NB1, CB_SHIFT);
    hist_kernel<<<(nnz2 + 255) / 256, 256>>>(idx2, nnz2, BASE2, 1, 31);
    hist_kernel<<<(nnz3 + 255) / 256, 256>>>(idx3, nnz3, BASE3, 1, 31);
    hist_kernel<<<(nnz4 + 255) / 256, 256>>>(idx4, nnz4, BASE4, 1, 31);
    hist_kernel<<<(nnz5 + 255) / 256, 256>>>(idx5, nnz5, BASE5, 1, 31);

    // 3) global exclusive scan -> positions into g_pairs
    scan_kernel<<<1, 1024>>>();

    // 4) scatter (col,val) pairs
    scatter_kernel<<<(nnz1 + 255) / 256, 256>>>(idx1, val1, nnz1, BASE1, NB1, CB_SHIFT);
    scatter_kernel<<<(nnz2 + 255) / 256, 256>>>(idx2, val2, nnz2, BASE2, 1, 31);
    scatter_kernel<<<(nnz3 + 255) / 256, 256>>>(idx3, val3, nnz3, BASE3, 1, 31);
    scatter_kernel<<<(nnz4 + 255) / 256, 256>>>(idx4, val4, nnz4, BASE4, 1, 31);
    scatter_kernel<<<(nnz5 + 255) / 256, 256>>>(idx5, val5, nnz5, BASE5, 1, 31);

    // 5) the five fused sparse-linear layers
    //    L1: spLinear + BN(g1) + silu     (dominant: 7.2M nnz)
    spmm_kernel<<<H1, 512>>>(xT, b1, g1, be1, h1, BASE1, NB1, 2, H1, 1);
    //    L2: spLinear + silu
    spmm_kernel<<<H1, 512>>>(h1, b2, (const float*)0, (const float*)0, h2, BASE2, 1, 1, H1, 1);
    //    L3: spLinear + BN(g2) + silu
    spmm_kernel<<<H2, 512>>>(h2, b3, g2, be2, h3, BASE3, 1, 2, H2, 1);
    //    L4: spLinear + BN(g3) + silu
    spmm_kernel<<<H3, 512>>>(h3, b4, g3, be3, h4, BASE4, 1, 2, H3, 1);
    //    L5: spLinear, write row-major [B, H3] to d_out
    spmm_kernel<<<H3, 512>>>(h4, b5, (const float*)0, (const float*)0,
                             (float*)d_out, BASE5, 1, 0, H3, 0);
}